// round 11
// baseline (speedup 1.0000x reference)
#include <cuda_runtime.h>
#include <cuda_fp16.h>
#include <cstdint>

// GraphAttention, 2-kernel split for 2-CTA/SM residency.
// K1 (batch x H-half, 512 CTAs): h_half = x@Ww_half^T + b, f/g partials -> global.
// K2 (batch x H-half, 512 CTAs): softmax alpha + out_half = alpha @ h_half.

#define B_ 256
#define C_ 128
#define T_ 512
#define H_ 256
#define HALF 128
#define KC 32
#define CHUNKS 16

// K1 smem: stages [0,40960): stage s at s*20480; x@+0 (128x40 fp16), W@+10240 (128x40 fp16)
//          hstg aliases [0,34816): 128 x 136 fp16. misc floats @40960.
#define K1_MISC 40960
#define K1_SMEM (40960 + 1408 * 4)
// K2 smem: alpha @0 (128x136 fp16 = 34816), htile @34816 (128x136), misc @69632
#define K2_AH 0
#define K2_HB 34816
#define K2_MISC 69632
#define K2_SMEM (69632 + 644 * 4)

__device__ __align__(16) __half g_h[(size_t)B_ * 2 * HALF * HALF];  // [b][nh][i][jj]
__device__ float g_fg[B_ * 2 * 2 * HALF];                            // [b][nh][f|g][i]

__device__ __forceinline__ uint32_t smem_u32(const void* p) {
    uint32_t a;
    asm("{ .reg .u64 t; cvta.to.shared.u64 t, %1; cvt.u32.u64 %0, t; }" : "=r"(a) : "l"(p));
    return a;
}
__device__ __forceinline__ void mma16(float* c, const uint32_t* a, const uint32_t* b) {
    asm volatile(
        "mma.sync.aligned.m16n8k16.row.col.f32.f16.f16.f32 "
        "{%0,%1,%2,%3}, {%4,%5,%6,%7}, {%8,%9}, {%0,%1,%2,%3};"
        : "+f"(c[0]), "+f"(c[1]), "+f"(c[2]), "+f"(c[3])
        : "r"(a[0]), "r"(a[1]), "r"(a[2]), "r"(a[3]), "r"(b[0]), "r"(b[1]));
}
__device__ __forceinline__ void ldm_x4(uint32_t* r, uint32_t addr) {
    asm volatile("ldmatrix.sync.aligned.m8n8.x4.shared.b16 {%0,%1,%2,%3}, [%4];"
        : "=r"(r[0]), "=r"(r[1]), "=r"(r[2]), "=r"(r[3]) : "r"(addr));
}
__device__ __forceinline__ void ldm_x4_t(uint32_t* r, uint32_t addr) {
    asm volatile("ldmatrix.sync.aligned.m8n8.x4.trans.shared.b16 {%0,%1,%2,%3}, [%4];"
        : "=r"(r[0]), "=r"(r[1]), "=r"(r[2]), "=r"(r[3]) : "r"(addr));
}
__device__ __forceinline__ uint32_t pack2(float lo, float hi) {
    __half2 h = __floats2half2_rn(lo, hi);
    return *(const uint32_t*)&h;
}
#define CP_ASYNC16(dst, src) \
    asm volatile("cp.async.cg.shared.global [%0], [%1], 16;" :: "r"(dst), "l"(src) : "memory")
#define CP_COMMIT() asm volatile("cp.async.commit_group;" ::: "memory")
#define CP_WAIT(n)  asm volatile("cp.async.wait_group %0;" :: "n"(n) : "memory")

// ---------------- K1: h_half + f/g partials ----------------
__global__ __launch_bounds__(256, 2)
void k1_h(const float* __restrict__ x, const float* __restrict__ Ww,
          const float* __restrict__ Wb, const float* __restrict__ aw)
{
    extern __shared__ char smc[];
    const uint32_t smb = smem_u32(smc);
    float* misc = (float*)(smc + K1_MISC);

    const int tid = threadIdx.x;
    const int lane = tid & 31, warp = tid >> 5;
    const int wr = warp >> 2;       // 0..1 -> 64-row block
    const int wc = warp & 3;        // 0..3 -> 32-col block
    const int lq = lane >> 2, lk = lane & 3;
    const int b = blockIdx.x >> 1, nh = blockIdx.x & 1;

    const int lrow = lane & 7, ga = (lane >> 3) & 1, gb = lane >> 4;
    const uint32_t a_roff = (uint32_t)(lrow + ga * 8);
    const uint32_t a_koff = (uint32_t)(gb * 8);
    const uint32_t b_roff = (uint32_t)(lrow + gb * 8);
    const uint32_t b_koff = (uint32_t)(ga * 8);

    const float* xb = x + (size_t)b * C_ * T_;
    const float* wsrc = Ww + (size_t)nh * HALF * T_;

    if (tid < 128) {
        misc[tid]       = Wb[nh * HALF + tid];
        misc[128 + tid] = aw[nh * HALF + tid];
        misc[256 + tid] = aw[H_ + nh * HALF + tid];
    }

    const int srow = tid >> 3;      // 0..127
    const int sslot = tid & 7;      // 0..7

    uint2 px[2], pw[2];             // packed fp16 prefetch (x: 2 float4 rows worth, W: 2)

    auto ldg_chunk = [&](int c) {
        #pragma unroll
        for (int i = 0; i < 2; i++) {
            // 512 float4 per tensor half? x: 128 rows x 8 slots = 1024 float4; 256 thr * 2 iters... need 4.
            // handled below with two pairs: this lambda does x; see ldg_w for W.
            float4 v = *(const float4*)(xb + ((srow + 0) * 0 + 0));
            (void)v; (void)c, (void)i;
        }
    };
    (void)ldg_chunk;

    // x: 1024 float4 -> 4 per thread; W: 1024 float4 -> 4 per thread.
    // Pack each float4 to uint2 at load time: px2[4], pw2[4].
    uint2 px2[4], pw2[4];
    auto ldgx = [&](int c) {
        #pragma unroll
        for (int i = 0; i < 4; i++) {
            int id = tid + i * 256;
            int row = id >> 3, slot = id & 7;
            float4 v = *(const float4*)(xb + row * T_ + c * KC + slot * 4);
            px2[i].x = pack2(v.x, v.y);
            px2[i].y = pack2(v.z, v.w);
        }
    };
    auto ldgw = [&](int c) {
        #pragma unroll
        for (int i = 0; i < 4; i++) {
            int id = tid + i * 256;
            int row = id >> 3, slot = id & 7;
            float4 v = *(const float4*)(wsrc + row * T_ + c * KC + slot * 4);
            pw2[i].x = pack2(v.x, v.y);
            pw2[i].y = pack2(v.z, v.w);
        }
    };
    auto sts_both = [&](int st) {
        #pragma unroll
        for (int i = 0; i < 4; i++) {
            int id = tid + i * 256;
            int row = id >> 3, slot = id & 7;
            *(uint2*)(smc + st + row * 80 + slot * 8) = px2[i];
            *(uint2*)(smc + st + 10240 + row * 80 + slot * 8) = pw2[i];
        }
    };
    (void)px; (void)pw;

    float acc[4][4][4];
    #pragma unroll
    for (int mb = 0; mb < 4; mb++)
        #pragma unroll
        for (int nb = 0; nb < 4; nb++)
            #pragma unroll
            for (int q = 0; q < 4; q++) acc[mb][nb][q] = 0.f;

    ldgx(0); ldgw(0);
    sts_both(0);
    ldgx(1); ldgw(1);

    for (int c = 0; c < CHUNKS; c++) {
        __syncthreads();
        if (c + 1 < CHUNKS) {
            sts_both((c + 1) & 1 ? 20480 : 0);
            if (c + 2 < CHUNKS) { ldgx(c + 2); ldgw(c + 2); }
        }
        const uint32_t xs_u = smb + (uint32_t)((c & 1) ? 20480 : 0);
        const uint32_t ws_u = xs_u + 10240u;

        #pragma unroll
        for (int kq = 0; kq < 2; kq++) {
            const uint32_t k0 = (uint32_t)(kq * 16);
            uint32_t afr[4][4];
            #pragma unroll
            for (int mb = 0; mb < 4; mb++)
                ldm_x4(afr[mb],
                    xs_u + (((uint32_t)(wr * 64 + mb * 16) + a_roff) * 40u + k0 + a_koff) * 2u);
            uint32_t bfr[2][4];
            #pragma unroll
            for (int nbp = 0; nbp < 2; nbp++)
                ldm_x4(bfr[nbp],
                    ws_u + (((uint32_t)(wc * 32 + nbp * 16) + b_roff) * 40u + k0 + b_koff) * 2u);
            #pragma unroll
            for (int mb = 0; mb < 4; mb++)
                #pragma unroll
                for (int nbp = 0; nbp < 2; nbp++) {
                    mma16(acc[mb][2 * nbp],     afr[mb], &bfr[nbp][0]);
                    mma16(acc[mb][2 * nbp + 1], afr[mb], &bfr[nbp][2]);
                }
        }
    }
    __syncthreads();

    // epilogue: bias, f/g partials, h fp16 -> smem tile (stride 136) aliasing stages
    {
        __half* hstg = (__half*)smc;
        #pragma unroll
        for (int mb = 0; mb < 4; mb++) {
            #pragma unroll
            for (int hf = 0; hf < 2; hf++) {
                int r = wr * 64 + mb * 16 + lq + hf * 8;
                float f_ = 0.f, g_ = 0.f;
                #pragma unroll
                for (int nb = 0; nb < 4; nb++) {
                    int col = wc * 32 + nb * 8 + 2 * lk;
                    float h0 = acc[mb][nb][hf * 2 + 0] + misc[col];
                    float h1 = acc[mb][nb][hf * 2 + 1] + misc[col + 1];
                    f_ += h0 * misc[128 + col] + h1 * misc[128 + col + 1];
                    g_ += h0 * misc[256 + col] + h1 * misc[256 + col + 1];
                    *(uint32_t*)(hstg + r * 136 + col) = pack2(h0, h1);
                }
                f_ += __shfl_xor_sync(0xFFFFFFFF, f_, 1);
                f_ += __shfl_xor_sync(0xFFFFFFFF, f_, 2);
                g_ += __shfl_xor_sync(0xFFFFFFFF, g_, 1);
                g_ += __shfl_xor_sync(0xFFFFFFFF, g_, 2);
                if (lk == 0) {
                    misc[384 + wc * 128 + r] = f_;
                    misc[896 + wc * 128 + r] = g_;
                }
            }
        }
    }
    __syncthreads();
    if (tid < 128) {
        float f = (misc[384 + tid] + misc[384 + 128 + tid]) +
                  (misc[384 + 256 + tid] + misc[384 + 384 + tid]);
        float g = (misc[896 + tid] + misc[896 + 128 + tid]) +
                  (misc[896 + 256 + tid] + misc[896 + 384 + tid]);
        g_fg[((b * 2 + nh) * 2 + 0) * HALF + tid] = f;
        g_fg[((b * 2 + nh) * 2 + 1) * HALF + tid] = g;
    }
    // coalesced h store: smem (stride 272B) -> global (stride 256B)
    {
        char* hdst = (char*)(g_h + (size_t)(b * 2 + nh) * HALF * HALF);
        #pragma unroll
        for (int i = 0; i < 8; i++) {
            int id = tid + i * 256;           // 2048 chunks of 16B
            int row = id >> 4, q = id & 15;
            uint4 v = *(const uint4*)(smc + row * 272 + q * 16);
            *(uint4*)(hdst + row * 256 + q * 16) = v;
        }
    }
}

// ---------------- K2: softmax + out_half ----------------
__global__ __launch_bounds__(256, 2)
void k2_out(const float* __restrict__ ab, float* __restrict__ out)
{
    extern __shared__ char smc[];
    const uint32_t smb = smem_u32(smc);
    float* misc = (float*)(smc + K2_MISC);
    float* fv = misc;            // 128
    float* gv = misc + 128;      // 128
    float* sp = misc + 256;      // 256
    float* sinv = misc + 512;    // 128

    const int tid = threadIdx.x;
    const int lane = tid & 31, warp = tid >> 5;
    const int wr = warp >> 2, wc = warp & 3;
    const int lq = lane >> 2, lk = lane & 3;
    const int b = blockIdx.x >> 1, nh = blockIdx.x & 1;

    const int lrow = lane & 7, ga = (lane >> 3) & 1, gb = lane >> 4;
    const uint32_t a_roff = (uint32_t)(lrow + ga * 8);
    const uint32_t a_koff = (uint32_t)(gb * 8);

    // start h tile cp.async (overlaps with softmax)
    {
        const char* hsrc = (const char*)(g_h + (size_t)(b * 2 + nh) * HALF * HALF);
        #pragma unroll
        for (int i = 0; i < 8; i++) {
            int id = tid + i * 256;
            int row = id >> 4, q = id & 15;
            CP_ASYNC16(smb + (uint32_t)(K2_HB + row * 272 + q * 16),
                       hsrc + row * 256 + q * 16);
        }
        CP_COMMIT();
    }

    if (tid < 128) {
        fv[tid] = g_fg[((b * 2 + 0) * 2 + 0) * HALF + tid] +
                  g_fg[((b * 2 + 1) * 2 + 0) * HALF + tid];
    } else {
        int r = tid - 128;
        gv[r] = g_fg[((b * 2 + 0) * 2 + 1) * HALF + r] +
                g_fg[((b * 2 + 1) * 2 + 1) * HALF + r];
    }
    if (tid == 0) misc[640] = ab[0];
    __syncthreads();

    // alpha[i][j], softmax over i per column j; fp16 stride 136
    {
        __half* ah = (__half*)(smc + K2_AH);
        const int j = tid & 127, part = tid >> 7;    // 2 parts x 64 i
        const float gj = gv[j] + misc[640];
        float s = 0.f;
        const int i0 = part * 64;
        #pragma unroll 4
        for (int i = i0; i < i0 + 64; i++) {
            float z = fv[i] + gj;
            z = (z > 0.f) ? z : 0.2f * z;
            float ex = __expf(z);
            ah[i * 136 + j] = __float2half_rn(ex);
            s += ex;
        }
        sp[part * 128 + j] = s;
        __syncthreads();
        if (tid < 128) sinv[tid] = 1.0f / (sp[tid] + sp[128 + tid]);
        __syncthreads();
        const float iv = sinv[j];
        #pragma unroll 4
        for (int i = i0; i < i0 + 64; i++) {
            __half* p = ah + i * 136 + j;
            *p = __float2half_rn(__half2float(*p) * iv);
        }
    }
    CP_WAIT(0);
    __syncthreads();

    // out_half = alpha @ h_half  (128x128x128)
    float acc[4][4][4];
    #pragma unroll
    for (int mb = 0; mb < 4; mb++)
        #pragma unroll
        for (int nb = 0; nb < 4; nb++)
            #pragma unroll
            for (int q = 0; q < 4; q++) acc[mb][nb][q] = 0.f;

    {
        const uint32_t ah_u = smb + K2_AH;
        const uint32_t ht_u = smb + K2_HB;
        #pragma unroll 2
        for (int kq = 0; kq < 8; kq++) {
            const uint32_t k0 = (uint32_t)(kq * 16);
            uint32_t afr[4][4];
            #pragma unroll
            for (int mb = 0; mb < 4; mb++)
                ldm_x4(afr[mb],
                    ah_u + (((uint32_t)(wr * 64 + mb * 16) + a_roff) * 136u + k0 + a_koff) * 2u);
            uint32_t bfr[2][4];
            #pragma unroll
            for (int nbp = 0; nbp < 2; nbp++)
                ldm_x4_t(bfr[nbp],
                    ht_u + ((k0 + a_roff) * 136u + (uint32_t)(wc * 32 + nbp * 16 + gb * 8)) * 2u);
            #pragma unroll
            for (int mb = 0; mb < 4; mb++)
                #pragma unroll
                for (int nbp = 0; nbp < 2; nbp++) {
                    mma16(acc[mb][2 * nbp],     afr[mb], &bfr[nbp][0]);
                    mma16(acc[mb][2 * nbp + 1], afr[mb], &bfr[nbp][2]);
                }
        }
    }

    {
        float* ob = out + (size_t)b * C_ * H_ + nh * HALF;
        #pragma unroll
        for (int mb = 0; mb < 4; mb++) {
            int r  = wr * 64 + mb * 16 + lq;
            int r2 = r + 8;
            #pragma unroll
            for (int nb = 0; nb < 4; nb++) {
                int j0 = wc * 32 + nb * 8 + 2 * lk;
                *(float2*)&ob[r  * H_ + j0] = make_float2(acc[mb][nb][0], acc[mb][nb][1]);
                *(float2*)&ob[r2 * H_ + j0] = make_float2(acc[mb][nb][2], acc[mb][nb][3]);
            }
        }
    }
}

extern "C" void kernel_launch(void* const* d_in, const int* in_sizes, int n_in,
                              void* d_out, int out_size)
{
    const float* x  = (const float*)d_in[0];
    const float* Ww = (const float*)d_in[1];
    const float* Wb = (const float*)d_in[2];
    const float* aw = (const float*)d_in[3];
    const float* ab = (const float*)d_in[4];
    float* out = (float*)d_out;

    cudaFuncSetAttribute(k1_h, cudaFuncAttributeMaxDynamicSharedMemorySize, K1_SMEM);
    cudaFuncSetAttribute(k2_out, cudaFuncAttributeMaxDynamicSharedMemorySize, K2_SMEM);

    k1_h<<<B_ * 2, 256, K1_SMEM>>>(x, Ww, Wb, aw);
    k2_out<<<B_ * 2, 256, K2_SMEM>>>(ab, out);
}

// round 13
// speedup vs baseline: 1.2898x; 1.2898x over previous
#include <cuda_runtime.h>
#include <cuda_fp16.h>
#include <cstdint>

// GraphAttention fused, fp16 m16n8k16 + ldmatrix + deep staging pipeline.
// K0: Ww -> fp16 (device global). KMain: fused phase1/2/3, 512 thr, 16 warps.
// W staged via cp.async (3 stages, distance 2); x via reg-prefetch (distance 3).

#define B_ 256
#define C_ 128
#define T_ 512
#define H_ 256
#define KC 32
#define CHUNKS 16
#define THREADS 512

#define XROW 40              // x/W stage row stride (halves); 80B, ldmatrix conflict-free
#define HTROW 264            // h row-major stride (halves)
#define AROW 136             // alpha row stride (halves)

// byte offsets in dynamic smem
#define XS(s) ((s) * 10240)            // x stages: 3 x 128*40*2
#define WS(s) (30720 + (s) * 20480)    // W stages: 3 x 256*40*2
#define HT_OFF 0                       // h row-major 128 x 264 fp16 = 67584 (aliases stages)
#define AH_OFF 67584                   // alpha 128 x 136 fp16 = 34816
#define MISCB  102400
// misc f32 indices
#define M_WB   0
#define M_ASRC 256
#define M_ADST 512
#define M_FP   768
#define M_GP   1792
#define M_FV   2816
#define M_GV   2944
#define M_SP   3072
#define M_SINV 3584
#define M_AB   3712
#define SMEM_BYTES (MISCB + 3720 * 4)

__device__ __align__(16) __half g_wh[H_ * T_];

__device__ __forceinline__ uint32_t smem_u32(const void* p) {
    uint32_t a;
    asm("{ .reg .u64 t; cvta.to.shared.u64 t, %1; cvt.u32.u64 %0, t; }" : "=r"(a) : "l"(p));
    return a;
}
__device__ __forceinline__ void mma16(float* c, const uint32_t* a, const uint32_t* b) {
    asm volatile(
        "mma.sync.aligned.m16n8k16.row.col.f32.f16.f16.f32 "
        "{%0,%1,%2,%3}, {%4,%5,%6,%7}, {%8,%9}, {%0,%1,%2,%3};"
        : "+f"(c[0]), "+f"(c[1]), "+f"(c[2]), "+f"(c[3])
        : "r"(a[0]), "r"(a[1]), "r"(a[2]), "r"(a[3]), "r"(b[0]), "r"(b[1]));
}
__device__ __forceinline__ void ldm_x4(uint32_t* r, uint32_t addr) {
    asm volatile("ldmatrix.sync.aligned.m8n8.x4.shared.b16 {%0,%1,%2,%3}, [%4];"
        : "=r"(r[0]), "=r"(r[1]), "=r"(r[2]), "=r"(r[3]) : "r"(addr));
}
__device__ __forceinline__ void ldm_x4_t(uint32_t* r, uint32_t addr) {
    asm volatile("ldmatrix.sync.aligned.m8n8.x4.trans.shared.b16 {%0,%1,%2,%3}, [%4];"
        : "=r"(r[0]), "=r"(r[1]), "=r"(r[2]), "=r"(r[3]) : "r"(addr));
}
__device__ __forceinline__ uint32_t pack2(float lo, float hi) {
    __half2 h = __floats2half2_rn(lo, hi);
    return *(const uint32_t*)&h;
}
#define CP_ASYNC16(dst, src) \
    asm volatile("cp.async.cg.shared.global [%0], [%1], 16;" :: "r"(dst), "l"(src) : "memory")
#define CP_COMMIT() asm volatile("cp.async.commit_group;" ::: "memory")
#define CP_WAIT(n)  asm volatile("cp.async.wait_group %0;" :: "n"(n) : "memory")

// ---------------- K0: Ww fp32 -> fp16 ----------------
__global__ void k0_convw(const float* __restrict__ Ww) {
    int i = blockIdx.x * 256 + threadIdx.x;   // grid (H_*T_)/256 = 512
    g_wh[i] = __float2half_rn(Ww[i]);
}

// ---------------- Main fused kernel ----------------
__global__ __launch_bounds__(THREADS, 1)
void gat_p(const float* __restrict__ x, const float* __restrict__ Wb,
           const float* __restrict__ aw, const float* __restrict__ ab,
           float* __restrict__ out)
{
    extern __shared__ char smc[];
    float* misc = (float*)(smc + MISCB);
    const uint32_t smb = smem_u32(smc);

    const int tid  = threadIdx.x;
    const int lane = tid & 31;
    const int warp = tid >> 5;
    const int wr   = warp >> 3;      // 0..1: 64-row block
    const int wc   = warp & 7;       // 0..7: 32-col block
    const int lq   = lane >> 2;
    const int lk   = lane & 3;
    const int b    = blockIdx.x;

    const int lrow = lane & 7, ga = (lane >> 3) & 1, gb = lane >> 4;
    const uint32_t a_roff = (uint32_t)(lrow + ga * 8);
    const uint32_t a_koff = (uint32_t)(gb * 8);
    const uint32_t b_roff = (uint32_t)(lrow + gb * 8);
    const uint32_t b_koff = (uint32_t)(ga * 8);

    const float* xb = x + (size_t)b * C_ * T_;

    if (tid < 256) {
        misc[M_WB + tid]   = Wb[tid];
        misc[M_ASRC + tid] = aw[tid];
        misc[M_ADST + tid] = aw[H_ + tid];
    }
    if (tid == 0) misc[M_AB] = ab[0];

    // x: 1024 float4/chunk -> 2 per thread, packed to fp16 at LDG time.
    // Buffer convention: px[k % 3] holds chunk k.
    uint2 px[3][2];

    auto ldgx = [&](int c, int s) {
        #pragma unroll
        for (int i = 0; i < 2; i++) {
            int id = tid + i * THREADS;                // < 1024
            int row = id >> 3, slot = id & 7;
            float4 v = *(const float4*)(xb + row * T_ + c * KC + slot * 4);
            px[s][i].x = pack2(v.x, v.y);
            px[s][i].y = pack2(v.z, v.w);
        }
    };
    auto stsx = [&](int s, int stage) {
        #pragma unroll
        for (int i = 0; i < 2; i++) {
            int id = tid + i * THREADS;
            int row = id >> 3, slot = id & 7;
            *(uint2*)(smc + XS(stage) + row * 80 + slot * 8) = px[s][i];
        }
    };
    auto cpaw = [&](int c, int stage) {
        #pragma unroll
        for (int i = 0; i < 2; i++) {
            int id = tid + i * THREADS;                // < 1024
            int row = id >> 2, q = id & 3;             // 256 rows x 4 x 16B
            CP_ASYNC16(smb + (uint32_t)(WS(stage) + row * 80 + q * 16),
                       g_wh + row * T_ + c * KC + q * 8);
        }
        CP_COMMIT();
    };

    float acc[4][4][4];
    #pragma unroll
    for (int mb = 0; mb < 4; mb++)
        #pragma unroll
        for (int nb = 0; nb < 4; nb++)
            #pragma unroll
            for (int q = 0; q < 4; q++) acc[mb][nb][q] = 0.f;

    // prologue: x dist-3 (regs), W dist-2 (cp.async)
    ldgx(0, 0); ldgx(1, 1); ldgx(2, 2);
    stsx(0, 0);
    cpaw(0, 0);
    cpaw(1, 1);

    // ---- Phase 1 ----
    #pragma unroll
    for (int c = 0; c < CHUNKS; c++) {
        if (c < CHUNKS - 1) CP_WAIT(1); else CP_WAIT(0);
        __syncthreads();
        if (c + 1 < CHUNKS) {
            stsx((c + 1) % 3, (c + 1) % 3);
            if (c + 3 < CHUNKS) ldgx(c + 3, (c + 3) % 3);   // buffer = chunk % 3
        }
        if (c + 2 < CHUNKS) cpaw(c + 2, (c + 2) % 3);

        const uint32_t xs_u = smb + (uint32_t)XS(c % 3);
        const uint32_t ws_u = smb + (uint32_t)WS(c % 3);

        #pragma unroll
        for (int kq = 0; kq < 2; kq++) {
            const uint32_t k0 = (uint32_t)(kq * 16);
            uint32_t afr[4][4];
            #pragma unroll
            for (int mb = 0; mb < 4; mb++)
                ldm_x4(afr[mb],
                    xs_u + (((uint32_t)(wr * 64 + mb * 16) + a_roff) * XROW + k0 + a_koff) * 2u);
            uint32_t bfr[2][4];
            #pragma unroll
            for (int nbp = 0; nbp < 2; nbp++)
                ldm_x4(bfr[nbp],
                    ws_u + (((uint32_t)(wc * 32 + nbp * 16) + b_roff) * XROW + k0 + b_koff) * 2u);
            #pragma unroll
            for (int mb = 0; mb < 4; mb++)
                #pragma unroll
                for (int nbp = 0; nbp < 2; nbp++) {
                    mma16(acc[mb][2 * nbp],     afr[mb], &bfr[nbp][0]);
                    mma16(acc[mb][2 * nbp + 1], afr[mb], &bfr[nbp][2]);
                }
        }
    }
    __syncthreads();

    // ---- Epilogue 1: bias, f/g partials, h row-major fp16 (stride 264) ----
    {
        __half* ht = (__half*)(smc + HT_OFF);
        #pragma unroll
        for (int mb = 0; mb < 4; mb++) {
            #pragma unroll
            for (int hf = 0; hf < 2; hf++) {
                int r = wr * 64 + mb * 16 + lq + hf * 8;
                float f_ = 0.f, g_ = 0.f;
                #pragma unroll
                for (int nb = 0; nb < 4; nb++) {
                    int col = wc * 32 + nb * 8 + 2 * lk;
                    float h0 = acc[mb][nb][hf * 2 + 0] + misc[M_WB + col];
                    float h1 = acc[mb][nb][hf * 2 + 1] + misc[M_WB + col + 1];
                    f_ += h0 * misc[M_ASRC + col] + h1 * misc[M_ASRC + col + 1];
                    g_ += h0 * misc[M_ADST + col] + h1 * misc[M_ADST + col + 1];
                    *(uint32_t*)(ht + r * HTROW + col) = pack2(h0, h1);
                }
                f_ += __shfl_xor_sync(0xFFFFFFFF, f_, 1);
                f_ += __shfl_xor_sync(0xFFFFFFFF, f_, 2);
                g_ += __shfl_xor_sync(0xFFFFFFFF, g_, 1);
                g_ += __shfl_xor_sync(0xFFFFFFFF, g_, 2);
                if (lk == 0) {
                    misc[M_FP + wc * 128 + r] = f_;
                    misc[M_GP + wc * 128 + r] = g_;
                }
            }
        }
    }
    __syncthreads();
    if (tid < 128) {
        float s = 0.f;
        #pragma unroll
        for (int p = 0; p < 8; p++) s += misc[M_FP + p * 128 + tid];
        misc[M_FV + tid] = s;
    } else if (tid < 256) {
        int r = tid - 128;
        float s = 0.f;
        #pragma unroll
        for (int p = 0; p < 8; p++) s += misc[M_GP + p * 128 + r];
        misc[M_GV + r] = s;
    }
    __syncthreads();

    // ---- Phase 2: softmax over i; alpha fp16 row-major [i][k=j] ----
    {
        __half* ah = (__half*)(smc + AH_OFF);
        const int j = tid & 127, part = tid >> 7;
        const float gj = misc[M_GV + j] + misc[M_AB];
        float s = 0.f;
        const int i0 = part * 32;
        #pragma unroll 4
        for (int i = i0; i < i0 + 32; i++) {
            float z = misc[M_FV + i] + gj;
            z = (z > 0.f) ? z : 0.2f * z;
            float ex = __expf(z);
            ah[i * AROW + j] = __float2half_rn(ex);
            s += ex;
        }
        misc[M_SP + part * 128 + j] = s;
        __syncthreads();
        if (tid < 128)
            misc[M_SINV + tid] = 1.0f /
                ((misc[M_SP + tid] + misc[M_SP + 128 + tid]) +
                 (misc[M_SP + 256 + tid] + misc[M_SP + 384 + tid]));
        __syncthreads();
        const float iv = misc[M_SINV + j];
        #pragma unroll 4
        for (int i = i0; i < i0 + 32; i++) {
            __half* p = ah + i * AROW + j;
            *p = __float2half_rn(__half2float(*p) * iv);
        }
    }
    __syncthreads();

    // ---- Phase 3: out = alpha @ h ----
    #pragma unroll
    for (int mb = 0; mb < 4; mb++)
        #pragma unroll
        for (int nb = 0; nb < 4; nb++)
            #pragma unroll
            for (int q = 0; q < 4; q++) acc[mb][nb][q] = 0.f;

    {
        const uint32_t ah_u = smb + AH_OFF;
        const uint32_t ht_u = smb + HT_OFF;
        #pragma unroll 2
        for (int kq = 0; kq < 8; kq++) {
            const uint32_t k0 = (uint32_t)(kq * 16);
            uint32_t afr[4][4];
            #pragma unroll
            for (int mb = 0; mb < 4; mb++)
                ldm_x4(afr[mb],
                    ah_u + (((uint32_t)(wr * 64 + mb * 16) + a_roff) * AROW + k0 + a_koff) * 2u);
            uint32_t bfr[2][4];
            #pragma unroll
            for (int nbp = 0; nbp < 2; nbp++)
                ldm_x4_t(bfr[nbp],
                    ht_u + ((k0 + a_roff) * HTROW + (uint32_t)(wc * 32 + nbp * 16 + gb * 8)) * 2u);
            #pragma unroll
            for (int mb = 0; mb < 4; mb++)
                #pragma unroll
                for (int nbp = 0; nbp < 2; nbp++) {
                    mma16(acc[mb][2 * nbp],     afr[mb], &bfr[nbp][0]);
                    mma16(acc[mb][2 * nbp + 1], afr[mb], &bfr[nbp][2]);
                }
        }
    }

    // ---- Epilogue 2: store out ----
    {
        float* ob = out + (size_t)b * C_ * H_;
        #pragma unroll
        for (int mb = 0; mb < 4; mb++) {
            int r  = wr * 64 + mb * 16 + lq;
            int r2 = r + 8;
            #pragma unroll
            for (int nb = 0; nb < 4; nb++) {
                int j0 = wc * 32 + nb * 8 + 2 * lk;
                *(float2*)&ob[r  * H_ + j0] = make_float2(acc[mb][nb][0], acc[mb][nb][1]);
                *(float2*)&ob[r2 * H_ + j0] = make_float2(acc[mb][nb][2], acc[mb][nb][3]);
            }
        }
    }
}

extern "C" void kernel_launch(void* const* d_in, const int* in_sizes, int n_in,
                              void* d_out, int out_size)
{
    const float* x  = (const float*)d_in[0];
    const float* Ww = (const float*)d_in[1];
    const float* Wb = (const float*)d_in[2];
    const float* aw = (const float*)d_in[3];
    const float* ab = (const float*)d_in[4];
    float* out = (float*)d_out;

    cudaFuncSetAttribute(gat_p, cudaFuncAttributeMaxDynamicSharedMemorySize, SMEM_BYTES);

    k0_convw<<<(H_ * T_) / 256, 256>>>(Ww);
    gat_p<<<B_, THREADS, SMEM_BYTES>>>(x, Wb, aw, ab, out);
}

// round 14
// speedup vs baseline: 1.3684x; 1.0610x over previous
#include <cuda_runtime.h>
#include <cuda_fp16.h>
#include <cstdint>

// GraphAttention fused, fp16 m16n8k16 + ldmatrix. KC=64 (8 chunks), 2-stage pipeline.
// K0: Ww -> fp16 (device global). Main: 512 thr, 16 warps (2x8, 64x32 warp tiles).

#define B_ 256
#define C_ 128
#define T_ 512
#define H_ 256
#define KC 64
#define CHUNKS 8
#define THREADS 512

#define XROW 72              // stage row stride (halves); 144B = 4-bank row step, conflict-free
#define HTROW 264            // h row-major stride (halves)
#define AROW 136             // alpha row stride (halves)

// byte offsets in dynamic smem
#define XS(s) ((s) * 18432)            // x stages: 2 x 128*72*2
#define WS(s) (36864 + (s) * 36864)    // W stages: 2 x 256*72*2
#define HT_OFF 0                       // h row-major 128 x 264 fp16 = 67584 (aliases stages)
#define AH_OFF 67584                   // alpha 128 x 136 fp16 = 34816
#define MISCB  110592
// misc f32 indices
#define M_WB   0
#define M_ASRC 256
#define M_ADST 512
#define M_FP   768
#define M_GP   1792
#define M_FV   2816
#define M_GV   2944
#define M_SP   3072
#define M_SINV 3584
#define M_AB   3712
#define SMEM_BYTES (MISCB + 3720 * 4)

__device__ __align__(16) __half g_wh[H_ * T_];

__device__ __forceinline__ uint32_t smem_u32(const void* p) {
    uint32_t a;
    asm("{ .reg .u64 t; cvta.to.shared.u64 t, %1; cvt.u32.u64 %0, t; }" : "=r"(a) : "l"(p));
    return a;
}
__device__ __forceinline__ void mma16(float* c, const uint32_t* a, const uint32_t* b) {
    asm volatile(
        "mma.sync.aligned.m16n8k16.row.col.f32.f16.f16.f32 "
        "{%0,%1,%2,%3}, {%4,%5,%6,%7}, {%8,%9}, {%0,%1,%2,%3};"
        : "+f"(c[0]), "+f"(c[1]), "+f"(c[2]), "+f"(c[3])
        : "r"(a[0]), "r"(a[1]), "r"(a[2]), "r"(a[3]), "r"(b[0]), "r"(b[1]));
}
__device__ __forceinline__ void ldm_x4(uint32_t* r, uint32_t addr) {
    asm volatile("ldmatrix.sync.aligned.m8n8.x4.shared.b16 {%0,%1,%2,%3}, [%4];"
        : "=r"(r[0]), "=r"(r[1]), "=r"(r[2]), "=r"(r[3]) : "r"(addr));
}
__device__ __forceinline__ void ldm_x4_t(uint32_t* r, uint32_t addr) {
    asm volatile("ldmatrix.sync.aligned.m8n8.x4.trans.shared.b16 {%0,%1,%2,%3}, [%4];"
        : "=r"(r[0]), "=r"(r[1]), "=r"(r[2]), "=r"(r[3]) : "r"(addr));
}
__device__ __forceinline__ uint32_t pack2(float lo, float hi) {
    __half2 h = __floats2half2_rn(lo, hi);
    return *(const uint32_t*)&h;
}
#define CP_ASYNC16(dst, src) \
    asm volatile("cp.async.cg.shared.global [%0], [%1], 16;" :: "r"(dst), "l"(src) : "memory")
#define CP_COMMIT() asm volatile("cp.async.commit_group;" ::: "memory")
#define CP_WAIT(n)  asm volatile("cp.async.wait_group %0;" :: "n"(n) : "memory")

// ---------------- K0: Ww fp32 -> fp16 ----------------
__global__ void k0_convw(const float* __restrict__ Ww) {
    int i = blockIdx.x * 256 + threadIdx.x;   // grid (H_*T_)/256 = 512
    g_wh[i] = __float2half_rn(Ww[i]);
}

// ---------------- Main fused kernel ----------------
__global__ __launch_bounds__(THREADS, 1)
void gat_p(const float* __restrict__ x, const float* __restrict__ Wb,
           const float* __restrict__ aw, const float* __restrict__ ab,
           float* __restrict__ out)
{
    extern __shared__ char smc[];
    float* misc = (float*)(smc + MISCB);
    const uint32_t smb = smem_u32(smc);

    const int tid  = threadIdx.x;
    const int lane = tid & 31;
    const int warp = tid >> 5;
    const int wr   = warp >> 3;      // 0..1: 64-row block
    const int wc   = warp & 7;       // 0..7: 32-col block
    const int lq   = lane >> 2;
    const int lk   = lane & 3;
    const int b    = blockIdx.x;

    const int lrow = lane & 7, ga = (lane >> 3) & 1, gb = lane >> 4;
    const uint32_t a_roff = (uint32_t)(lrow + ga * 8);
    const uint32_t a_koff = (uint32_t)(gb * 8);
    const uint32_t b_roff = (uint32_t)(lrow + gb * 8);
    const uint32_t b_koff = (uint32_t)(ga * 8);

    const float* xb = x + (size_t)b * C_ * T_;

    if (tid < 256) {
        misc[M_WB + tid]   = Wb[tid];
        misc[M_ASRC + tid] = aw[tid];
        misc[M_ADST + tid] = aw[H_ + tid];
    }
    if (tid == 0) misc[M_AB] = ab[0];

    // x: chunk = 128 rows x 64 cols fp32 = 2048 float4 -> 4 per thread, packed at LDG.
    // Buffer convention: px[k & 1] holds chunk k.
    uint2 px[2][4];

    auto ldgx = [&](int c, int s) {
        #pragma unroll
        for (int i = 0; i < 4; i++) {
            int id = tid + i * THREADS;                // < 2048
            int row = id >> 4, slot = id & 15;
            float4 v = *(const float4*)(xb + row * T_ + c * KC + slot * 4);
            px[s][i].x = pack2(v.x, v.y);
            px[s][i].y = pack2(v.z, v.w);
        }
    };
    auto stsx = [&](int s, int stage) {
        #pragma unroll
        for (int i = 0; i < 4; i++) {
            int id = tid + i * THREADS;
            int row = id >> 4, slot = id & 15;
            *(uint2*)(smc + XS(stage) + row * 144 + slot * 8) = px[s][i];
        }
    };
    auto cpaw = [&](int c, int stage) {
        #pragma unroll
        for (int i = 0; i < 4; i++) {
            int id = tid + i * THREADS;                // < 2048
            int row = id >> 3, q = id & 7;             // 256 rows x 8 x 16B
            CP_ASYNC16(smb + (uint32_t)(WS(stage) + row * 144 + q * 16),
                       g_wh + row * T_ + c * KC + q * 8);
        }
        CP_COMMIT();
    };

    float acc[4][4][4];
    #pragma unroll
    for (int mb = 0; mb < 4; mb++)
        #pragma unroll
        for (int nb = 0; nb < 4; nb++)
            #pragma unroll
            for (int q = 0; q < 4; q++) acc[mb][nb][q] = 0.f;

    // prologue
    ldgx(0, 0);
    ldgx(1, 1);
    cpaw(0, 0);
    stsx(0, 0);
    CP_WAIT(0);
    __syncthreads();

    // ---- Phase 1 ----
    #pragma unroll
    for (int c = 0; c < CHUNKS; c++) {
        if (c + 1 < CHUNKS) {
            cpaw(c + 1, (c + 1) & 1);
            stsx((c + 1) & 1, (c + 1) & 1);
        }
        if (c + 2 < CHUNKS) ldgx(c + 2, c & 1);   // px[c&1] free (chunk c already staged)

        const uint32_t xs_u = smb + (uint32_t)XS(c & 1);
        const uint32_t ws_u = smb + (uint32_t)WS(c & 1);

        #pragma unroll
        for (int kq = 0; kq < 4; kq++) {
            const uint32_t k0 = (uint32_t)(kq * 16);
            uint32_t afr[4][4];
            #pragma unroll
            for (int mb = 0; mb < 4; mb++)
                ldm_x4(afr[mb],
                    xs_u + (((uint32_t)(wr * 64 + mb * 16) + a_roff) * XROW + k0 + a_koff) * 2u);
            uint32_t bfr[2][4];
            #pragma unroll
            for (int nbp = 0; nbp < 2; nbp++)
                ldm_x4(bfr[nbp],
                    ws_u + (((uint32_t)(wc * 32 + nbp * 16) + b_roff) * XROW + k0 + b_koff) * 2u);
            #pragma unroll
            for (int mb = 0; mb < 4; mb++)
                #pragma unroll
                for (int nbp = 0; nbp < 2; nbp++) {
                    mma16(acc[mb][2 * nbp],     afr[mb], &bfr[nbp][0]);
                    mma16(acc[mb][2 * nbp + 1], afr[mb], &bfr[nbp][2]);
                }
        }
        if (c + 1 < CHUNKS) CP_WAIT(0);
        __syncthreads();
    }

    // ---- Epilogue 1: bias, f/g partials, h row-major fp16 (stride 264) ----
    {
        __half* ht = (__half*)(smc + HT_OFF);
        #pragma unroll
        for (int mb = 0; mb < 4; mb++) {
            #pragma unroll
            for (int hf = 0; hf < 2; hf++) {
                int r = wr * 64 + mb * 16 + lq + hf * 8;
                float f_ = 0.f, g_ = 0.f;
                #pragma unroll
                for (int nb = 0; nb < 4; nb++) {
                    int col = wc * 32 + nb * 8 + 2 * lk;
                    float h0 = acc[mb][nb][hf * 2 + 0] + misc[M_WB + col];
                    float h1 = acc[mb][nb][hf * 2 + 1] + misc[M_WB + col + 1];
                    f_ += h0 * misc[M_ASRC + col] + h1 * misc[M_ASRC + col + 1];
                    g_ += h0 * misc[M_ADST + col] + h1 * misc[M_ADST + col + 1];
                    *(uint32_t*)(ht + r * HTROW + col) = pack2(h0, h1);
                }
                f_ += __shfl_xor_sync(0xFFFFFFFF, f_, 1);
                f_ += __shfl_xor_sync(0xFFFFFFFF, f_, 2);
                g_ += __shfl_xor_sync(0xFFFFFFFF, g_, 1);
                g_ += __shfl_xor_sync(0xFFFFFFFF, g_, 2);
                if (lk == 0) {
                    misc[M_FP + wc * 128 + r] = f_;
                    misc[M_GP + wc * 128 + r] = g_;
                }
            }
        }
    }
    __syncthreads();
    if (tid < 128) {
        float s = 0.f;
        #pragma unroll
        for (int p = 0; p < 8; p++) s += misc[M_FP + p * 128 + tid];
        misc[M_FV + tid] = s;
    } else if (tid < 256) {
        int r = tid - 128;
        float s = 0.f;
        #pragma unroll
        for (int p = 0; p < 8; p++) s += misc[M_GP + p * 128 + r];
        misc[M_GV + r] = s;
    }
    __syncthreads();

    // ---- Phase 2: softmax over i; alpha fp16 row-major [i][k=j] ----
    {
        __half* ah = (__half*)(smc + AH_OFF);
        const int j = tid & 127, part = tid >> 7;
        const float gj = misc[M_GV + j] + misc[M_AB];
        float s = 0.f;
        const int i0 = part * 32;
        #pragma unroll 4
        for (int i = i0; i < i0 + 32; i++) {
            float z = misc[M_FV + i] + gj;
            z = (z > 0.f) ? z : 0.2f * z;
            float ex = __expf(z);
            ah[i * AROW + j] = __float2half_rn(ex);
            s += ex;
        }
        misc[M_SP + part * 128 + j] = s;
        __syncthreads();
        if (tid < 128)
            misc[M_SINV + tid] = 1.0f /
                ((misc[M_SP + tid] + misc[M_SP + 128 + tid]) +
                 (misc[M_SP + 256 + tid] + misc[M_SP + 384 + tid]));
        __syncthreads();
        const float iv = misc[M_SINV + j];
        #pragma unroll 4
        for (int i = i0; i < i0 + 32; i++) {
            __half* p = ah + i * AROW + j;
            *p = __float2half_rn(__half2float(*p) * iv);
        }
    }
    __syncthreads();

    // ---- Phase 3: out = alpha @ h ----
    #pragma unroll
    for (int mb = 0; mb < 4; mb++)
        #pragma unroll
        for (int nb = 0; nb < 4; nb++)
            #pragma unroll
            for (int q = 0; q < 4; q++) acc[mb][nb][q] = 0.f;

    {
        const uint32_t ah_u = smb + AH_OFF;
        const uint32_t ht_u = smb + HT_OFF;
        #pragma unroll 2
        for (int kq = 0; kq < 8; kq++) {
            const uint32_t k0 = (uint32_t)(kq * 16);
            uint32_t afr[4][4];
            #pragma unroll
            for (int mb = 0; mb < 4; mb++)
                ldm_x4(afr[mb],
                    ah_u + (((uint32_t)(wr * 64 + mb * 16) + a_roff) * AROW + k0 + a_koff) * 2u);
            uint32_t bfr[2][4];
            #pragma unroll
            for (int nbp = 0; nbp < 2; nbp++)
                ldm_x4_t(bfr[nbp],
                    ht_u + ((k0 + a_roff) * HTROW + (uint32_t)(wc * 32 + nbp * 16 + gb * 8)) * 2u);
            #pragma unroll
            for (int mb = 0; mb < 4; mb++)
                #pragma unroll
                for (int nbp = 0; nbp < 2; nbp++) {
                    mma16(acc[mb][2 * nbp],     afr[mb], &bfr[nbp][0]);
                    mma16(acc[mb][2 * nbp + 1], afr[mb], &bfr[nbp][2]);
                }
        }
    }

    // ---- Epilogue 2: store out ----
    {
        float* ob = out + (size_t)b * C_ * H_;
        #pragma unroll
        for (int mb = 0; mb < 4; mb++) {
            int r  = wr * 64 + mb * 16 + lq;
            int r2 = r + 8;
            #pragma unroll
            for (int nb = 0; nb < 4; nb++) {
                int j0 = wc * 32 + nb * 8 + 2 * lk;
                *(float2*)&ob[r  * H_ + j0] = make_float2(acc[mb][nb][0], acc[mb][nb][1]);
                *(float2*)&ob[r2 * H_ + j0] = make_float2(acc[mb][nb][2], acc[mb][nb][3]);
            }
        }
    }
}

extern "C" void kernel_launch(void* const* d_in, const int* in_sizes, int n_in,
                              void* d_out, int out_size)
{
    const float* x  = (const float*)d_in[0];
    const float* Ww = (const float*)d_in[1];
    const float* Wb = (const float*)d_in[2];
    const float* aw = (const float*)d_in[3];
    const float* ab = (const float*)d_in[4];
    float* out = (float*)d_out;

    cudaFuncSetAttribute(gat_p, cudaFuncAttributeMaxDynamicSharedMemorySize, SMEM_BYTES);

    k0_convw<<<(H_ * T_) / 256, 256>>>(Ww);
    gat_p<<<B_, THREADS, SMEM_BYTES>>>(x, Wb, aw, ab, out);
}